// round 1
// baseline (speedup 1.0000x reference)
#include <cuda_runtime.h>
#include <math.h>

// Problem constants (shapes fixed by the dataset):
//   X:               [N, 6]    fp32   (in_sizes[0] = 6N)
//   linear_mappings: [768, 72] fp32   (3C x E, C=256, E=72)
//   centroids:       [256, 3]  fp32
//   out:             [N, 3]    fp32
constexpr int NC      = 256;           // clusters
constexpr int EDIM    = 72;            // posenc dim (6 dims * 2 * 6 freqs)
constexpr int WROWS   = 768;           // 3*NC
constexpr int WELEMS  = WROWS * EDIM;  // 55296 floats = 221184 B
constexpr int SMEM_FLOATS = WELEMS + NC * 3;        // + centroids
constexpr int SMEM_BYTES  = SMEM_FLOATS * 4;        // 224256 B (<227KB cap)

constexpr int TPB = 384;  // 12 warps; 1 CTA/SM (smem-limited), ~105 regs/thread

__global__ __launch_bounds__(TPB, 1)
void rgb_fused_kernel(const float* __restrict__ X,
                      const float* __restrict__ W,
                      const float* __restrict__ cent,
                      float* __restrict__ out, int N)
{
    extern __shared__ float smem[];
    float* sW = smem;            // [768][72]
    float* sC = smem + WELEMS;   // [256][3]

    // Cooperative load of W (float4-vectorized, coalesced) + centroids.
    {
        float4* dst = reinterpret_cast<float4*>(sW);
        const float4* src = reinterpret_cast<const float4*>(W);
        for (int i = threadIdx.x; i < WELEMS / 4; i += TPB) dst[i] = src[i];
        for (int i = threadIdx.x; i < NC * 3; i += TPB) sC[i] = cent[i];
    }
    __syncthreads();

    const int n = blockIdx.x * TPB + threadIdx.x;
    if (n >= N) return;

    float x[6];
#pragma unroll
    for (int d = 0; d < 6; ++d) x[d] = X[n * 6 + d];

    // Positional encoding: enc[d*12 + f] = sin(2^f x_d), enc[d*12 + 6 + f] = cos(2^f x_d).
    // Frequencies are powers of two -> one accurate sincos per dim + double-angle
    // recurrence (avoids MUFU large-argument range-reduction error under fast-math).
    float enc[EDIM];
#pragma unroll
    for (int d = 0; d < 6; ++d) {
        float s, c;
        sincosf(x[d], &s, &c);
#pragma unroll
        for (int k = 0; k < 6; ++k) {
            enc[d * 12 + k]     = s;
            enc[d * 12 + 6 + k] = c;
            float s2 = 2.0f * s * c;
            float c2 = fmaf(-2.0f * s, s, 1.0f);  // cos(2a) = 1 - 2 sin^2 a
            s = s2;
            c = c2;
        }
    }

    // Single-pass softmax-weighted contraction:
    //   r_d = sum_c exp(s_c) * (enc . W[3c+d]),  Z = sum_c exp(s_c),  rgb_d = r_d / Z
    // No max-subtraction needed: |s_c| = |x[:3].centroid| << 88.
    float r0 = 0.f, r1 = 0.f, r2 = 0.f, Z = 0.f;

    for (int c = 0; c < NC; ++c) {
        const float sc = fmaf(x[0], sC[c * 3 + 0],
                         fmaf(x[1], sC[c * 3 + 1],
                              x[2] * sC[c * 3 + 2]));
        const float wgt = __expf(sc);
        Z += wgt;

        const float4* w0 = reinterpret_cast<const float4*>(sW + (3 * c + 0) * EDIM);
        const float4* w1 = reinterpret_cast<const float4*>(sW + (3 * c + 1) * EDIM);
        const float4* w2 = reinterpret_cast<const float4*>(sW + (3 * c + 2) * EDIM);

        // 6 independent accumulator chains (2 per output channel) for FMA ILP.
        float a0 = 0.f, b0 = 0.f, a1 = 0.f, b1 = 0.f, a2 = 0.f, b2 = 0.f;
#pragma unroll
        for (int j = 0; j < 18; j += 2) {
            float4 u, v;
            u = w0[j]; v = w0[j + 1];
            a0 = fmaf(enc[4 * j + 0], u.x, a0);
            a0 = fmaf(enc[4 * j + 1], u.y, a0);
            a0 = fmaf(enc[4 * j + 2], u.z, a0);
            a0 = fmaf(enc[4 * j + 3], u.w, a0);
            b0 = fmaf(enc[4 * j + 4], v.x, b0);
            b0 = fmaf(enc[4 * j + 5], v.y, b0);
            b0 = fmaf(enc[4 * j + 6], v.z, b0);
            b0 = fmaf(enc[4 * j + 7], v.w, b0);

            u = w1[j]; v = w1[j + 1];
            a1 = fmaf(enc[4 * j + 0], u.x, a1);
            a1 = fmaf(enc[4 * j + 1], u.y, a1);
            a1 = fmaf(enc[4 * j + 2], u.z, a1);
            a1 = fmaf(enc[4 * j + 3], u.w, a1);
            b1 = fmaf(enc[4 * j + 4], v.x, b1);
            b1 = fmaf(enc[4 * j + 5], v.y, b1);
            b1 = fmaf(enc[4 * j + 6], v.z, b1);
            b1 = fmaf(enc[4 * j + 7], v.w, b1);

            u = w2[j]; v = w2[j + 1];
            a2 = fmaf(enc[4 * j + 0], u.x, a2);
            a2 = fmaf(enc[4 * j + 1], u.y, a2);
            a2 = fmaf(enc[4 * j + 2], u.z, a2);
            a2 = fmaf(enc[4 * j + 3], u.w, a2);
            b2 = fmaf(enc[4 * j + 4], v.x, b2);
            b2 = fmaf(enc[4 * j + 5], v.y, b2);
            b2 = fmaf(enc[4 * j + 6], v.z, b2);
            b2 = fmaf(enc[4 * j + 7], v.w, b2);
        }

        r0 = fmaf(wgt, a0 + b0, r0);
        r1 = fmaf(wgt, a1 + b1, r1);
        r2 = fmaf(wgt, a2 + b2, r2);
    }

    const float inv = 1.0f / Z;
    out[n * 3 + 0] = r0 * inv;
    out[n * 3 + 1] = r1 * inv;
    out[n * 3 + 2] = r2 * inv;
}

extern "C" void kernel_launch(void* const* d_in, const int* in_sizes, int n_in,
                              void* d_out, int out_size)
{
    const float* X    = (const float*)d_in[0];  // [N, 6]
    const float* W    = (const float*)d_in[1];  // [768, 72]
    const float* cent = (const float*)d_in[2];  // [256, 3]
    float* out = (float*)d_out;                 // [N, 3]

    const int N = in_sizes[0] / 6;

    // Opt in to >48KB dynamic smem (idempotent, host-side, not a stream op —
    // safe under graph capture).
    cudaFuncSetAttribute(rgb_fused_kernel,
                         cudaFuncAttributeMaxDynamicSharedMemorySize, SMEM_BYTES);

    const int grid = (N + TPB - 1) / TPB;
    rgb_fused_kernel<<<grid, TPB, SMEM_BYTES>>>(X, W, cent, out, N);
}

// round 3
// speedup vs baseline: 5.8200x; 5.8200x over previous
#include <cuda_runtime.h>
#include <cuda_fp16.h>
#include <stdint.h>

// rgb[n,d] = (1/Z_n) * sum_e enc[n,e] * D[n, d*72+e]
// D = A @ W',  A[n,c] = exp2(s'_nc - max_c),  s' = x[:3] . (centroid_c * log2e)
// W'[c, j=d*72+e] = W[3c+d, e]  (fp16, smem-resident, loaded once per CTA)
// GEMM per 128-point tile via mma.sync.m16n8k16 (f16 in, f32 accum).

constexpr int TPB    = 256;
constexpr int TILE_M = 128;
constexpr int NC     = 256;
constexpr int EDIM   = 72;
constexpr int NOUT   = 216;

constexpr int ROW_B   = 528;   // bytes per A/W' smem row: 256 halfs + 8 pad (16B-aligned, conflict-free LDSM)
constexpr int ENC_F   = 74;    // floats per enc row (72 + 2 pad)

constexpr int OFF_CENT = 0;                          // 256 * float4 = 4096
constexpr int OFF_WP   = 4096;                       // 216 * 528   = 114048
constexpr int OFF_A    = OFF_WP + NOUT * ROW_B;      // 118144 ; 128*528 = 67584
constexpr int OFF_ENC  = OFF_A + TILE_M * ROW_B;     // 185728 ; 128*74*4 = 37888
constexpr int OFF_RED0 = OFF_ENC + TILE_M * ENC_F * 4;  // 223616 ; 1024
constexpr int OFF_RED1 = OFF_RED0 + 1024;            // 224640 ; 1024
constexpr int OFF_INVZ = OFF_RED1 + 1024;            // 225664 ; 512
constexpr int OFF_RACC = OFF_INVZ + 512;             // 226176 ; 128*16 = 2048
constexpr int SMEM_BYTES = OFF_RACC + TILE_M * 16;   // 228224 (< 227KB cap)

constexpr float LOG2E = 1.4426950408889634f;

__device__ __forceinline__ uint32_t s2u(const void* p) {
    uint32_t a;
    asm("{ .reg .u64 t; cvta.to.shared.u64 t, %1; cvt.u32.u64 %0, t; }"
        : "=r"(a) : "l"(p));
    return a;
}

__device__ __forceinline__ void ldsm4(uint32_t* r, uint32_t addr) {
    asm volatile("ldmatrix.sync.aligned.m8n8.x4.shared.b16 {%0,%1,%2,%3}, [%4];"
                 : "=r"(r[0]), "=r"(r[1]), "=r"(r[2]), "=r"(r[3]) : "r"(addr));
}
__device__ __forceinline__ void ldsm2(uint32_t* r, uint32_t addr) {
    asm volatile("ldmatrix.sync.aligned.m8n8.x2.shared.b16 {%0,%1}, [%2];"
                 : "=r"(r[0]), "=r"(r[1]) : "r"(addr));
}
__device__ __forceinline__ void hmma(float& d0, float& d1, float& d2, float& d3,
                                     const uint32_t* a, const uint32_t* b) {
    asm volatile("mma.sync.aligned.m16n8k16.row.col.f32.f16.f16.f32 "
                 "{%0,%1,%2,%3}, {%4,%5,%6,%7}, {%8,%9}, {%0,%1,%2,%3};"
                 : "+f"(d0), "+f"(d1), "+f"(d2), "+f"(d3)
                 : "r"(a[0]), "r"(a[1]), "r"(a[2]), "r"(a[3]), "r"(b[0]), "r"(b[1]));
}

__global__ __launch_bounds__(TPB, 1)
void rgb_hmma_kernel(const float* __restrict__ X,
                     const float* __restrict__ W,
                     const float* __restrict__ cent,
                     float* __restrict__ out, int N, int n_tiles)
{
    extern __shared__ char smem[];
    const uint32_t sb = s2u(smem);
    float4* c4   = reinterpret_cast<float4*>(smem + OFF_CENT);
    __half* wp   = reinterpret_cast<__half*>(smem + OFF_WP);
    __half* at   = reinterpret_cast<__half*>(smem + OFF_A);
    float* encS  = reinterpret_cast<float*>(smem + OFF_ENC);
    float* red0  = reinterpret_cast<float*>(smem + OFF_RED0);
    float* red1  = reinterpret_cast<float*>(smem + OFF_RED1);
    float* invZ  = reinterpret_cast<float*>(smem + OFF_INVZ);
    float* racc  = reinterpret_cast<float*>(smem + OFF_RACC);

    const int tid = threadIdx.x;

    // ---- one-time: centroids (pre-scaled by log2 e) + W' gather/transpose to fp16 ----
    for (int i = tid; i < NC; i += TPB) {
        float4 q;
        q.x = cent[i * 3 + 0] * LOG2E;
        q.y = cent[i * 3 + 1] * LOG2E;
        q.z = cent[i * 3 + 2] * LOG2E;
        q.w = 0.f;
        c4[i] = q;
    }
    for (int i = tid; i < 768 * EDIM; i += TPB) {
        int r = i / EDIM, e = i - r * EDIM;
        int c = r / 3, d = r - 3 * c;
        int j = d * EDIM + e;                       // W'[c][j] stored as row j, col c
        wp[j * (ROW_B / 2) + c] = __float2half_rn(W[i]);
    }
    __syncthreads();

    const int pt = tid & 127;
    const int h  = tid >> 7;            // cluster-half this thread owns
    const int w  = tid >> 5, l = tid & 31;
    const int m0 = w * 16;              // this warp's m-tile rows

    for (int tile = blockIdx.x; tile < n_tiles; tile += gridDim.x) {
        const int p = tile * TILE_M + pt;

        float x0 = 0.f, x1 = 0.f, x2 = 0.f;
        if (p < N) { x0 = X[p * 6 + 0]; x1 = X[p * 6 + 1]; x2 = X[p * 6 + 2]; }

        // ---- enc (threads < 128, one point each) ----
        if (tid < TILE_M) {
            float x[6] = {x0, x1, x2, 0.f, 0.f, 0.f};
            if (p < N) { x[3] = X[p * 6 + 3]; x[4] = X[p * 6 + 4]; x[5] = X[p * 6 + 5]; }
            float* er = encS + pt * ENC_F;
#pragma unroll
            for (int d = 0; d < 6; ++d) {
                float s, c;
                __sincosf(x[d], &s, &c);
#pragma unroll
                for (int k = 0; k < 6; ++k) {
                    er[d * 12 + k]     = s;
                    er[d * 12 + 6 + k] = c;
                    float s2 = 2.f * s * c;
                    float c2 = fmaf(-2.f * s, s, 1.f);
                    s = s2; c = c2;
                }
            }
        }

        // ---- softmax pass 1: partial max over this thread's 128 clusters ----
        const float4* cb = c4 + h * 128;
        float pm = -1e30f;
#pragma unroll 4
        for (int c = 0; c < 128; ++c) {
            float4 q = cb[c];
            pm = fmaxf(pm, fmaf(x0, q.x, fmaf(x1, q.y, x2 * q.z)));
        }
        red0[tid] = pm;
        racc[tid] = 0.f;                 // zero accumulators (safe: after prev tile's end-sync)
        racc[tid + 256] = 0.f;
        __syncthreads();

        // ---- softmax pass 2: exp2, Z (from fp16-rounded weights), pack A tile ----
        const float mx = fmaxf(red0[pt], red0[pt + 128]);
        float z = 0.f, wlo = 0.f;
        __half* arow = at + pt * (ROW_B / 2) + h * 128;
#pragma unroll 4
        for (int c = 0; c < 128; ++c) {
            float4 q = cb[c];
            float s = fmaf(x0, q.x, fmaf(x1, q.y, x2 * q.z)) - mx;
            float wv;
            asm("ex2.approx.ftz.f32 %0, %1;" : "=f"(wv) : "f"(s));
            if (c & 1) {
                __half2 h2 = __floats2half2_rn(wlo, wv);
                z += __low2float(h2) + __high2float(h2);   // Z from rounded weights
                *reinterpret_cast<__half2*>(arow + (c - 1)) = h2;
            } else {
                wlo = wv;
            }
        }
        red1[tid] = z;
        __syncthreads();
        if (tid < TILE_M) invZ[tid] = __frcp_rn(red1[tid] + red1[tid + 128]);

        // ---- GEMM: warp owns m-tile, caches 16 A k-fragments, sweeps 27 n-strips ----
        uint32_t a[16][4];
        {
            const uint32_t a_base = sb + OFF_A
                + (uint32_t)((m0 + (l & 15)) * ROW_B + (l >> 4) * 16);
#pragma unroll
            for (int kk = 0; kk < 16; ++kk)
                ldsm4(a[kk], a_base + kk * 32);
        }

        const int row0 = m0 + (l >> 2);
        const float* er0 = encS + row0 * ENC_F;
        const float* er1 = er0 + 8 * ENC_F;
        const uint32_t b_base = sb + OFF_WP
            + (uint32_t)((l & 7) * ROW_B + ((l >> 3) & 1) * 16);

#pragma unroll
        for (int dch = 0; dch < 3; ++dch) {       // d-block: strips never straddle (72/8=9)
            float accA = 0.f, accB = 0.f;
#pragma unroll 3
            for (int ss = 0; ss < 9; ++ss) {
                const int n0 = (dch * 9 + ss) * 8;
                uint32_t b[16][2];
#pragma unroll
                for (int kk = 0; kk < 16; ++kk)
                    ldsm2(b[kk], b_base + (uint32_t)(n0 * ROW_B) + kk * 32);
                // two accumulator chains to break HMMA RAW dependency
                float p0 = 0.f, p1 = 0.f, p2 = 0.f, p3 = 0.f;
                float q0 = 0.f, q1 = 0.f, q2 = 0.f, q3 = 0.f;
#pragma unroll
                for (int kk = 0; kk < 16; kk += 2) {
                    hmma(p0, p1, p2, p3, a[kk],     b[kk]);
                    hmma(q0, q1, q2, q3, a[kk + 1], b[kk + 1]);
                }
                const float d0 = p0 + q0, d1 = p1 + q1, d2 = p2 + q2, d3 = p3 + q3;
                const int e0 = n0 - 72 * dch + 2 * (l & 3);
                accA = fmaf(d0, er0[e0], fmaf(d1, er0[e0 + 1], accA));
                accB = fmaf(d2, er1[e0], fmaf(d3, er1[e0 + 1], accB));
            }
            atomicAdd(&racc[row0 * 4 + dch], accA);
            atomicAdd(&racc[(row0 + 8) * 4 + dch], accB);
        }
        __syncthreads();

        // ---- write out ----
        if (tid < TILE_M && p < N) {
            const float iz = invZ[tid];
            out[p * 3 + 0] = racc[tid * 4 + 0] * iz;
            out[p * 3 + 1] = racc[tid * 4 + 1] * iz;
            out[p * 3 + 2] = racc[tid * 4 + 2] * iz;
        }
        __syncthreads();
    }
}

extern "C" void kernel_launch(void* const* d_in, const int* in_sizes, int n_in,
                              void* d_out, int out_size)
{
    const float* X    = (const float*)d_in[0];  // [N, 6]
    const float* W    = (const float*)d_in[1];  // [768, 72]
    const float* cent = (const float*)d_in[2];  // [256, 3]
    float* out = (float*)d_out;                 // [N, 3]

    const int N = in_sizes[0] / 6;
    const int n_tiles = (N + TILE_M - 1) / TILE_M;

    int dev = 0, sms = 148;
    cudaGetDevice(&dev);
    cudaDeviceGetAttribute(&sms, cudaDevAttrMultiProcessorCount, dev);

    cudaFuncSetAttribute(rgb_hmma_kernel,
                         cudaFuncAttributeMaxDynamicSharedMemorySize, SMEM_BYTES);

    const int grid = n_tiles < sms ? n_tiles : sms;
    rgb_hmma_kernel<<<grid, TPB, SMEM_BYTES>>>(X, W, cent, out, N, n_tiles);
}

// round 4
// speedup vs baseline: 6.2462x; 1.0732x over previous
#include <cuda_runtime.h>
#include <cuda_fp16.h>
#include <stdint.h>

// rgb[n,d] = (1/Z_n) * sum_e enc[n,e] * D[n, d*72+e]
// D = A @ W',  A[n,c] = exp2(s'_nc - max_c),  s' = x[:3] . (centroid_c * log2e)
// W'[c, j=d*72+e] = W[3c+d, e]  (fp16, smem-resident, loaded once per CTA)
// GEMM per 128-point tile via mma.sync.m16n8k16; 16 warps = 8(m-tiles) x 2(n-halves).

constexpr int TPB    = 512;
constexpr int TILE_M = 128;
constexpr int NC     = 256;
constexpr int EDIM   = 72;
constexpr int NOUT   = 216;

constexpr int ROW_B  = 528;   // A/W' smem row bytes: 256 halfs + pad (16B-aligned, LDSM conflict-free)
constexpr int ENC_F  = 74;    // floats per enc row

constexpr int OFF_CENT = 0;                             // 4096
constexpr int OFF_WP   = 4096;                          // 216*528 = 114048
constexpr int OFF_A    = OFF_WP + NOUT * ROW_B;         // 118144
constexpr int OFF_ENC  = OFF_A + TILE_M * ROW_B;        // 185728
constexpr int OFF_RED0 = OFF_ENC + TILE_M * ENC_F * 4;  // 223616 (512 floats)
constexpr int OFF_RED1 = OFF_RED0 + 2048;               // 225664 (512 floats)
constexpr int OFF_INVZ = OFF_RED1 + 2048;               // 227712 (128 floats)
constexpr int OFF_RACC = OFF_INVZ + 512;                // 228224 (512 floats)
constexpr int SMEM_BYTES = OFF_RACC + 2048;             // 230272 (< 232448 cap)

constexpr float LOG2E = 1.4426950408889634f;

__device__ __forceinline__ uint32_t s2u(const void* p) {
    uint32_t a;
    asm("{ .reg .u64 t; cvta.to.shared.u64 t, %1; cvt.u32.u64 %0, t; }"
        : "=r"(a) : "l"(p));
    return a;
}
__device__ __forceinline__ void ldsm4(uint32_t* r, uint32_t addr) {
    asm volatile("ldmatrix.sync.aligned.m8n8.x4.shared.b16 {%0,%1,%2,%3}, [%4];"
                 : "=r"(r[0]), "=r"(r[1]), "=r"(r[2]), "=r"(r[3]) : "r"(addr));
}
__device__ __forceinline__ void ldsm2(uint32_t* r, uint32_t addr) {
    asm volatile("ldmatrix.sync.aligned.m8n8.x2.shared.b16 {%0,%1}, [%2];"
                 : "=r"(r[0]), "=r"(r[1]) : "r"(addr));
}
__device__ __forceinline__ void hmma(float& d0, float& d1, float& d2, float& d3,
                                     const uint32_t* a, const uint32_t* b) {
    asm volatile("mma.sync.aligned.m16n8k16.row.col.f32.f16.f16.f32 "
                 "{%0,%1,%2,%3}, {%4,%5,%6,%7}, {%8,%9}, {%0,%1,%2,%3};"
                 : "+f"(d0), "+f"(d1), "+f"(d2), "+f"(d3)
                 : "r"(a[0]), "r"(a[1]), "r"(a[2]), "r"(a[3]), "r"(b[0]), "r"(b[1]));
}

// One n-strip (8 output columns): load 16 B k-fragments, 16 HMMAs (2 chains),
// contract the 4 accumulators with enc in-register.
#define DO_STRIP(S, DCH, ACC_A, ACC_B)                                          \
    {                                                                           \
        const int n0 = (S) * 8;                                                 \
        uint32_t b[16][2];                                                      \
        _Pragma("unroll")                                                       \
        for (int kk = 0; kk < 16; ++kk)                                         \
            ldsm2(b[kk], b_base + (uint32_t)(n0 * ROW_B) + kk * 32);            \
        float p0 = 0.f, p1 = 0.f, p2 = 0.f, p3 = 0.f;                           \
        float q0 = 0.f, q1 = 0.f, q2 = 0.f, q3 = 0.f;                           \
        _Pragma("unroll")                                                       \
        for (int kk = 0; kk < 16; kk += 2) {                                    \
            hmma(p0, p1, p2, p3, a[kk],     b[kk]);                             \
            hmma(q0, q1, q2, q3, a[kk + 1], b[kk + 1]);                         \
        }                                                                       \
        const int e0 = n0 - 72 * (DCH) + 2 * (l & 3);                           \
        const float2 ev0 = *reinterpret_cast<const float2*>(er0 + e0);          \
        const float2 ev1 = *reinterpret_cast<const float2*>(er1 + e0);          \
        ACC_A = fmaf(p0 + q0, ev0.x, fmaf(p1 + q1, ev0.y, ACC_A));              \
        ACC_B = fmaf(p2 + q2, ev1.x, fmaf(p3 + q3, ev1.y, ACC_B));              \
    }

__global__ __launch_bounds__(TPB, 1)
void rgb_hmma_kernel(const float* __restrict__ X,
                     const float* __restrict__ W,
                     const float* __restrict__ cent,
                     float* __restrict__ out, int N, int n_tiles)
{
    extern __shared__ char smem[];
    const uint32_t sb = s2u(smem);
    float4* c4  = reinterpret_cast<float4*>(smem + OFF_CENT);
    __half* wp  = reinterpret_cast<__half*>(smem + OFF_WP);
    __half* at  = reinterpret_cast<__half*>(smem + OFF_A);
    float* encS = reinterpret_cast<float*>(smem + OFF_ENC);
    float* red0 = reinterpret_cast<float*>(smem + OFF_RED0);
    float* red1 = reinterpret_cast<float*>(smem + OFF_RED1);
    float* invZ = reinterpret_cast<float*>(smem + OFF_INVZ);
    float* racc = reinterpret_cast<float*>(smem + OFF_RACC);

    const int tid = threadIdx.x;

    // ---- one-time: centroids (pre-scaled by log2 e) + W' gather/transpose to fp16 ----
    for (int i = tid; i < NC; i += TPB) {
        float4 q;
        q.x = cent[i * 3 + 0] * LOG2E;
        q.y = cent[i * 3 + 1] * LOG2E;
        q.z = cent[i * 3 + 2] * LOG2E;
        q.w = 0.f;
        c4[i] = q;
    }
    for (int i = tid; i < 768 * EDIM; i += TPB) {
        int r = i / EDIM, e = i - r * EDIM;
        int c = r / 3, d = r - 3 * c;
        wp[(d * EDIM + e) * (ROW_B / 2) + c] = __float2half_rn(W[i]);
    }
    __syncthreads();

    const int pt = tid & 127;          // point within tile
    const int q  = tid >> 7;           // cluster quarter (0..3)
    const int w  = tid >> 5, l = tid & 31;
    const int mw = w & 7, nh = w >> 3; // warp's m-tile / n-half
    const int m0 = mw * 16;

    for (int tile = blockIdx.x; tile < n_tiles; tile += gridDim.x) {
        const int p = tile * TILE_M + pt;

        float x0 = 0.f, x1 = 0.f, x2 = 0.f;
        if (p < N) { x0 = X[p * 6 + 0]; x1 = X[p * 6 + 1]; x2 = X[p * 6 + 2]; }

        // ---- enc (threads < 128: one point each) ----
        if (tid < TILE_M) {
            float x[6] = {x0, x1, x2, 0.f, 0.f, 0.f};
            if (p < N) { x[3] = X[p * 6 + 3]; x[4] = X[p * 6 + 4]; x[5] = X[p * 6 + 5]; }
            float* er = encS + pt * ENC_F;
#pragma unroll
            for (int d = 0; d < 6; ++d) {
                float s, c;
                __sincosf(x[d], &s, &c);
#pragma unroll
                for (int k = 0; k < 6; ++k) {
                    er[d * 12 + k]     = s;
                    er[d * 12 + 6 + k] = c;
                    float s2 = 2.f * s * c;
                    float c2 = fmaf(-2.f * s, s, 1.f);
                    s = s2; c = c2;
                }
            }
        }

        // ---- softmax pass 1: partial max over this thread's 64 clusters ----
        const float4* cb = c4 + q * 64;
        float pm = -1e30f;
#pragma unroll 4
        for (int c = 0; c < 64; ++c) {
            float4 cq = cb[c];
            pm = fmaxf(pm, fmaf(x0, cq.x, fmaf(x1, cq.y, x2 * cq.z)));
        }
        red0[tid] = pm;
        racc[tid] = 0.f;
        __syncthreads();

        // ---- softmax pass 2: exp2, partial Z (fp16-rounded), pack A quarter ----
        const float mx = fmaxf(fmaxf(red0[pt], red0[pt + 128]),
                               fmaxf(red0[pt + 256], red0[pt + 384]));
        float z = 0.f, wlo = 0.f;
        __half* arow = at + pt * (ROW_B / 2) + q * 64;
#pragma unroll 4
        for (int c = 0; c < 64; ++c) {
            float4 cq = cb[c];
            float s = fmaf(x0, cq.x, fmaf(x1, cq.y, x2 * cq.z)) - mx;
            float wv;
            asm("ex2.approx.ftz.f32 %0, %1;" : "=f"(wv) : "f"(s));
            if (c & 1) {
                __half2 h2 = __floats2half2_rn(wlo, wv);
                z += __low2float(h2) + __high2float(h2);   // Z from rounded weights
                *reinterpret_cast<__half2*>(arow + (c - 1)) = h2;
            } else {
                wlo = wv;
            }
        }
        red1[tid] = z;
        __syncthreads();
        if (tid < TILE_M)
            invZ[tid] = __frcp_rn((red1[tid] + red1[tid + 128]) +
                                  (red1[tid + 256] + red1[tid + 384]));

        // ---- GEMM: warp caches 16 A k-fragments, sweeps its 13/14 n-strips ----
        uint32_t a[16][4];
        {
            const uint32_t a_base = sb + OFF_A
                + (uint32_t)((m0 + (l & 15)) * ROW_B + (l >> 4) * 16);
#pragma unroll
            for (int kk = 0; kk < 16; ++kk)
                ldsm4(a[kk], a_base + kk * 32);
        }

        const int row0 = m0 + (l >> 2);
        const float* er0 = encS + row0 * ENC_F;
        const float* er1 = er0 + 8 * ENC_F;
        const uint32_t b_base = sb + OFF_WP
            + (uint32_t)((l & 7) * ROW_B + ((l >> 3) & 1) * 16);

        if (nh == 0) {
            float aA0 = 0.f, aB0 = 0.f, aA1 = 0.f, aB1 = 0.f;
#pragma unroll
            for (int s = 0; s < 9; ++s)  DO_STRIP(s, 0, aA0, aB0);
#pragma unroll
            for (int s = 9; s < 13; ++s) DO_STRIP(s, 1, aA1, aB1);
            atomicAdd(&racc[row0 * 4 + 0], aA0);
            atomicAdd(&racc[(row0 + 8) * 4 + 0], aB0);
            atomicAdd(&racc[row0 * 4 + 1], aA1);
            atomicAdd(&racc[(row0 + 8) * 4 + 1], aB1);
        } else {
            float aA1 = 0.f, aB1 = 0.f, aA2 = 0.f, aB2 = 0.f;
#pragma unroll
            for (int s = 13; s < 18; ++s) DO_STRIP(s, 1, aA1, aB1);
#pragma unroll
            for (int s = 18; s < 27; ++s) DO_STRIP(s, 2, aA2, aB2);
            atomicAdd(&racc[row0 * 4 + 1], aA1);
            atomicAdd(&racc[(row0 + 8) * 4 + 1], aB1);
            atomicAdd(&racc[row0 * 4 + 2], aA2);
            atomicAdd(&racc[(row0 + 8) * 4 + 2], aB2);
        }
        __syncthreads();

        // ---- write out ----
        if (tid < TILE_M && p < N) {
            const float iz = invZ[tid];
            out[p * 3 + 0] = racc[tid * 4 + 0] * iz;
            out[p * 3 + 1] = racc[tid * 4 + 1] * iz;
            out[p * 3 + 2] = racc[tid * 4 + 2] * iz;
        }
        __syncthreads();
    }
}

extern "C" void kernel_launch(void* const* d_in, const int* in_sizes, int n_in,
                              void* d_out, int out_size)
{
    const float* X    = (const float*)d_in[0];  // [N, 6]
    const float* W    = (const float*)d_in[1];  // [768, 72]
    const float* cent = (const float*)d_in[2];  // [256, 3]
    float* out = (float*)d_out;                 // [N, 3]

    const int N = in_sizes[0] / 6;
    const int n_tiles = (N + TILE_M - 1) / TILE_M;

    int dev = 0, sms = 148;
    cudaGetDevice(&dev);
    cudaDeviceGetAttribute(&sms, cudaDevAttrMultiProcessorCount, dev);

    cudaFuncSetAttribute(rgb_hmma_kernel,
                         cudaFuncAttributeMaxDynamicSharedMemorySize, SMEM_BYTES);

    const int grid = n_tiles < sms ? n_tiles : sms;
    rgb_hmma_kernel<<<grid, TPB, SMEM_BYTES>>>(X, W, cent, out, N, n_tiles);
}

// round 5
// speedup vs baseline: 6.5783x; 1.0532x over previous
#include <cuda_runtime.h>
#include <cuda_fp16.h>
#include <stdint.h>

// rgb[n,d] = (1/Z_n) * sum_e enc[n,e] * D[n, d*72+e]
// D = A @ W',  A[n,c] = exp2(s'_nc - max_c),  s' = x[:3] . (centroid_c * log2e)
// W'[c, j=d*72+e] = W[3c+d, e]  (fp16, smem-resident, loaded once per CTA)
// GEMM per 128-point tile via mma.sync.m16n8k16.
// 16 warps = 4 m-groups (32 rows) x 2 k-halves (128) x 2 n-halves (~108).
// B fragments loaded as ldsm4 strip-pairs (full crossbar efficiency).

constexpr int TPB    = 512;
constexpr int TILE_M = 128;
constexpr int NC     = 256;
constexpr int EDIM   = 72;
constexpr int NOUT   = 216;

constexpr int ROW_B  = 528;   // A/W' smem row bytes: 256 halfs + pad (LDSM conflict-free)
constexpr int ENC_F  = 74;    // floats per enc row

constexpr int OFF_CENT = 0;                             // 4096
constexpr int OFF_WP   = 4096;                          // 216*528 = 114048
constexpr int OFF_A    = OFF_WP + NOUT * ROW_B;         // 118144
constexpr int OFF_ENC  = OFF_A + TILE_M * ROW_B;        // 185728
constexpr int OFF_RED0 = OFF_ENC + TILE_M * ENC_F * 4;  // 223616 (512 floats)
constexpr int OFF_RED1 = OFF_RED0 + 2048;               // 225664 (512 floats)
constexpr int OFF_INVZ = OFF_RED1 + 2048;               // 227712 (128 floats)
constexpr int OFF_RACC = OFF_INVZ + 512;                // 228224 (512 floats)
constexpr int SMEM_BYTES = OFF_RACC + 2048;             // 230272

constexpr float LOG2E = 1.4426950408889634f;

__device__ __forceinline__ uint32_t s2u(const void* p) {
    uint32_t a;
    asm("{ .reg .u64 t; cvta.to.shared.u64 t, %1; cvt.u32.u64 %0, t; }"
        : "=r"(a) : "l"(p));
    return a;
}
__device__ __forceinline__ void ldsm4(uint32_t* r, uint32_t addr) {
    asm volatile("ldmatrix.sync.aligned.m8n8.x4.shared.b16 {%0,%1,%2,%3}, [%4];"
                 : "=r"(r[0]), "=r"(r[1]), "=r"(r[2]), "=r"(r[3]) : "r"(addr));
}
__device__ __forceinline__ void ldsm2(uint32_t* r, uint32_t addr) {
    asm volatile("ldmatrix.sync.aligned.m8n8.x2.shared.b16 {%0,%1}, [%2];"
                 : "=r"(r[0]), "=r"(r[1]) : "r"(addr));
}
__device__ __forceinline__ void hmma(float& d0, float& d1, float& d2, float& d3,
                                     const uint32_t* a, const uint32_t* b) {
    asm volatile("mma.sync.aligned.m16n8k16.row.col.f32.f16.f16.f32 "
                 "{%0,%1,%2,%3}, {%4,%5,%6,%7}, {%8,%9}, {%0,%1,%2,%3};"
                 : "+f"(d0), "+f"(d1), "+f"(d2), "+f"(d3)
                 : "r"(a[0]), "r"(a[1]), "r"(a[2]), "r"(a[3]), "r"(b[0]), "r"(b[1]));
}

// Strip-pair: ldsm4 B frags for two adjacent 8-col strips (k-half = 8 ksteps),
// 32 HMMAs (4 independent chains), fold D into per-(mt,half,slot) accumulators.
template<int SL0, int SL1>
__device__ __forceinline__ void gemm_pair(
    uint32_t bbase, const uint32_t (&a)[2][8][4], int eo0, int eo1,
    const float* er00, const float* er01, const float* er10, const float* er11,
    float (&acc)[2][2][2])
{
    float d[2][2][4];
#pragma unroll
    for (int mt = 0; mt < 2; ++mt)
#pragma unroll
        for (int st = 0; st < 2; ++st)
#pragma unroll
            for (int i = 0; i < 4; ++i) d[mt][st][i] = 0.f;

#pragma unroll
    for (int hb = 0; hb < 2; ++hb) {
        uint32_t b[4][4];
#pragma unroll
        for (int kk = 0; kk < 4; ++kk)
            ldsm4(b[kk], bbase + (hb * 4 + kk) * 32);
#pragma unroll
        for (int kk = 0; kk < 4; ++kk)
#pragma unroll
            for (int mt = 0; mt < 2; ++mt) {
                hmma(d[mt][0][0], d[mt][0][1], d[mt][0][2], d[mt][0][3],
                     a[mt][hb * 4 + kk], &b[kk][0]);
                hmma(d[mt][1][0], d[mt][1][1], d[mt][1][2], d[mt][1][3],
                     a[mt][hb * 4 + kk], &b[kk][2]);
            }
    }
    {
        float2 e;
        e = *reinterpret_cast<const float2*>(er00 + eo0);
        acc[0][0][SL0] = fmaf(d[0][0][0], e.x, fmaf(d[0][0][1], e.y, acc[0][0][SL0]));
        e = *reinterpret_cast<const float2*>(er01 + eo0);
        acc[0][1][SL0] = fmaf(d[0][0][2], e.x, fmaf(d[0][0][3], e.y, acc[0][1][SL0]));
        e = *reinterpret_cast<const float2*>(er10 + eo0);
        acc[1][0][SL0] = fmaf(d[1][0][0], e.x, fmaf(d[1][0][1], e.y, acc[1][0][SL0]));
        e = *reinterpret_cast<const float2*>(er11 + eo0);
        acc[1][1][SL0] = fmaf(d[1][0][2], e.x, fmaf(d[1][0][3], e.y, acc[1][1][SL0]));
        e = *reinterpret_cast<const float2*>(er00 + eo1);
        acc[0][0][SL1] = fmaf(d[0][1][0], e.x, fmaf(d[0][1][1], e.y, acc[0][0][SL1]));
        e = *reinterpret_cast<const float2*>(er01 + eo1);
        acc[0][1][SL1] = fmaf(d[0][1][2], e.x, fmaf(d[0][1][3], e.y, acc[0][1][SL1]));
        e = *reinterpret_cast<const float2*>(er10 + eo1);
        acc[1][0][SL1] = fmaf(d[1][1][0], e.x, fmaf(d[1][1][1], e.y, acc[1][0][SL1]));
        e = *reinterpret_cast<const float2*>(er11 + eo1);
        acc[1][1][SL1] = fmaf(d[1][1][2], e.x, fmaf(d[1][1][3], e.y, acc[1][1][SL1]));
    }
}

template<int SL>
__device__ __forceinline__ void gemm_single(
    uint32_t bbase2, const uint32_t (&a)[2][8][4], int eo,
    const float* er00, const float* er01, const float* er10, const float* er11,
    float (&acc)[2][2][2])
{
    float d[2][4];
#pragma unroll
    for (int mt = 0; mt < 2; ++mt)
#pragma unroll
        for (int i = 0; i < 4; ++i) d[mt][i] = 0.f;
    uint32_t b[8][2];
#pragma unroll
    for (int kk = 0; kk < 8; ++kk) ldsm2(b[kk], bbase2 + kk * 32);
#pragma unroll
    for (int kk = 0; kk < 8; ++kk)
#pragma unroll
        for (int mt = 0; mt < 2; ++mt)
            hmma(d[mt][0], d[mt][1], d[mt][2], d[mt][3], a[mt][kk], b[kk]);
    float2 e;
    e = *reinterpret_cast<const float2*>(er00 + eo);
    acc[0][0][SL] = fmaf(d[0][0], e.x, fmaf(d[0][1], e.y, acc[0][0][SL]));
    e = *reinterpret_cast<const float2*>(er01 + eo);
    acc[0][1][SL] = fmaf(d[0][2], e.x, fmaf(d[0][3], e.y, acc[0][1][SL]));
    e = *reinterpret_cast<const float2*>(er10 + eo);
    acc[1][0][SL] = fmaf(d[1][0], e.x, fmaf(d[1][1], e.y, acc[1][0][SL]));
    e = *reinterpret_cast<const float2*>(er11 + eo);
    acc[1][1][SL] = fmaf(d[1][2], e.x, fmaf(d[1][3], e.y, acc[1][1][SL]));
}

__global__ __launch_bounds__(TPB, 1)
void rgb_hmma_kernel(const float* __restrict__ X,
                     const float* __restrict__ W,
                     const float* __restrict__ cent,
                     float* __restrict__ out, int N, int n_tiles)
{
    extern __shared__ char smem[];
    const uint32_t sb = s2u(smem);
    float4* c4  = reinterpret_cast<float4*>(smem + OFF_CENT);
    __half* wp  = reinterpret_cast<__half*>(smem + OFF_WP);
    __half* at  = reinterpret_cast<__half*>(smem + OFF_A);
    float* encS = reinterpret_cast<float*>(smem + OFF_ENC);
    float* red0 = reinterpret_cast<float*>(smem + OFF_RED0);
    float* red1 = reinterpret_cast<float*>(smem + OFF_RED1);
    float* invZ = reinterpret_cast<float*>(smem + OFF_INVZ);
    float* racc = reinterpret_cast<float*>(smem + OFF_RACC);

    const int tid = threadIdx.x;

    for (int i = tid; i < NC; i += TPB) {
        float4 qv;
        qv.x = cent[i * 3 + 0] * LOG2E;
        qv.y = cent[i * 3 + 1] * LOG2E;
        qv.z = cent[i * 3 + 2] * LOG2E;
        qv.w = 0.f;
        c4[i] = qv;
    }
    for (int i = tid; i < 768 * EDIM; i += TPB) {
        int r = i / EDIM, e = i - r * EDIM;
        int c = r / 3, d = r - 3 * c;
        wp[(d * EDIM + e) * (ROW_B / 2) + c] = __float2half_rn(W[i]);
    }
    __syncthreads();

    const int pt = tid & 127;
    const int q  = tid >> 7;                 // cluster quarter
    const int w  = tid >> 5, l = tid & 31;
    const int mw = w & 3, kh = (w >> 2) & 1, nh = w >> 3;

    for (int tile = blockIdx.x; tile < n_tiles; tile += gridDim.x) {
        const int p = tile * TILE_M + pt;

        float x0 = 0.f, x1 = 0.f, x2 = 0.f;
        if (p < N) { x0 = X[p * 6 + 0]; x1 = X[p * 6 + 1]; x2 = X[p * 6 + 2]; }

        // ---- enc (threads < 128) ----
        if (tid < TILE_M) {
            float x[6] = {x0, x1, x2, 0.f, 0.f, 0.f};
            if (p < N) { x[3] = X[p * 6 + 3]; x[4] = X[p * 6 + 4]; x[5] = X[p * 6 + 5]; }
            float* er = encS + pt * ENC_F;
#pragma unroll
            for (int d = 0; d < 6; ++d) {
                float s, c;
                __sincosf(x[d], &s, &c);
#pragma unroll
                for (int k = 0; k < 6; ++k) {
                    er[d * 12 + k]     = s;
                    er[d * 12 + 6 + k] = c;
                    float s2 = 2.f * s * c;
                    float c2 = fmaf(-2.f * s, s, 1.f);
                    s = s2; c = c2;
                }
            }
        }

        // ---- softmax pass 1: partial max over 64 clusters ----
        const float4* cb = c4 + q * 64;
        float pm = -1e30f;
#pragma unroll 4
        for (int c = 0; c < 64; ++c) {
            float4 cq = cb[c];
            pm = fmaxf(pm, fmaf(x0, cq.x, fmaf(x1, cq.y, x2 * cq.z)));
        }
        red0[tid] = pm;
        racc[tid] = 0.f;
        __syncthreads();

        // ---- softmax pass 2: exp2, partial Z (fp16-rounded), pack A quarter ----
        const float mx = fmaxf(fmaxf(red0[pt], red0[pt + 128]),
                               fmaxf(red0[pt + 256], red0[pt + 384]));
        float z = 0.f, wlo = 0.f;
        __half* arow = at + pt * (ROW_B / 2) + q * 64;
#pragma unroll 4
        for (int c = 0; c < 64; ++c) {
            float4 cq = cb[c];
            float s = fmaf(x0, cq.x, fmaf(x1, cq.y, x2 * cq.z)) - mx;
            float wv;
            asm("ex2.approx.ftz.f32 %0, %1;" : "=f"(wv) : "f"(s));
            if (c & 1) {
                __half2 h2 = __floats2half2_rn(wlo, wv);
                z += __low2float(h2) + __high2float(h2);
                *reinterpret_cast<__half2*>(arow + (c - 1)) = h2;
            } else {
                wlo = wv;
            }
        }
        red1[tid] = z;
        __syncthreads();
        if (tid < TILE_M)
            invZ[tid] = __frcp_rn((red1[tid] + red1[tid + 128]) +
                                  (red1[tid + 256] + red1[tid + 384]));

        // ---- GEMM: warp = (m-group 32, k-half 128, n-half) ----
        uint32_t a[2][8][4];
        {
            const uint32_t a_base = sb + OFF_A
                + (uint32_t)((mw * 32 + (l & 15)) * ROW_B + kh * 256 + (l >> 4) * 16);
#pragma unroll
            for (int mt = 0; mt < 2; ++mt)
#pragma unroll
                for (int kk = 0; kk < 8; ++kk)
                    ldsm4(a[mt][kk], a_base + mt * 16 * ROW_B + kk * 32);
        }

        const int lq = l >> 2;
        const int rr = mw * 32 + lq;
        const float* er00 = encS + rr * ENC_F + 2 * (l & 3);
        const float* er01 = er00 + 8 * ENC_F;
        const float* er10 = er00 + 16 * ENC_F;
        const float* er11 = er00 + 24 * ENC_F;

        const uint32_t bl2 = sb + OFF_WP
            + (uint32_t)((l & 7) * ROW_B + ((l >> 3) & 1) * 16 + kh * 256);
        const uint32_t bl4 = bl2 + (uint32_t)(((l >> 4) & 1) * 8 * ROW_B);

        float acc[2][2][2];
#pragma unroll
        for (int mt = 0; mt < 2; ++mt)
#pragma unroll
            for (int hf = 0; hf < 2; ++hf)
#pragma unroll
                for (int sl = 0; sl < 2; ++sl) acc[mt][hf][sl] = 0.f;

        if (nh == 0) {   // strips 0..13 : dch0 = s0..8, dch1 = s9..13
            gemm_pair<0, 0>(bl4 + 0  * 8 * ROW_B, a, 0,  8,  er00, er01, er10, er11, acc);
            gemm_pair<0, 0>(bl4 + 2  * 8 * ROW_B, a, 16, 24, er00, er01, er10, er11, acc);
            gemm_pair<0, 0>(bl4 + 4  * 8 * ROW_B, a, 32, 40, er00, er01, er10, er11, acc);
            gemm_pair<0, 0>(bl4 + 6  * 8 * ROW_B, a, 48, 56, er00, er01, er10, er11, acc);
            gemm_pair<0, 1>(bl4 + 8  * 8 * ROW_B, a, 64, 0,  er00, er01, er10, er11, acc);
            gemm_pair<1, 1>(bl4 + 10 * 8 * ROW_B, a, 8,  16, er00, er01, er10, er11, acc);
            gemm_pair<1, 1>(bl4 + 12 * 8 * ROW_B, a, 24, 32, er00, er01, er10, er11, acc);
        } else {         // strips 14..26 : dch1 = s14..17, dch2 = s18..26
            gemm_pair<0, 0>(bl4 + 14 * 8 * ROW_B, a, 40, 48, er00, er01, er10, er11, acc);
            gemm_pair<0, 0>(bl4 + 16 * 8 * ROW_B, a, 56, 64, er00, er01, er10, er11, acc);
            gemm_pair<1, 1>(bl4 + 18 * 8 * ROW_B, a, 0,  8,  er00, er01, er10, er11, acc);
            gemm_pair<1, 1>(bl4 + 20 * 8 * ROW_B, a, 16, 24, er00, er01, er10, er11, acc);
            gemm_pair<1, 1>(bl4 + 22 * 8 * ROW_B, a, 32, 40, er00, er01, er10, er11, acc);
            gemm_pair<1, 1>(bl4 + 24 * 8 * ROW_B, a, 48, 56, er00, er01, er10, er11, acc);
            gemm_single<1>(bl2 + 26 * 8 * ROW_B, a, 64, er00, er01, er10, er11, acc);
        }

        // ---- quad-reduce + atomic into racc[row*4 + dch] ----
#pragma unroll
        for (int mt = 0; mt < 2; ++mt)
#pragma unroll
            for (int hf = 0; hf < 2; ++hf)
#pragma unroll
                for (int sl = 0; sl < 2; ++sl) {
                    float v = acc[mt][hf][sl];
                    v += __shfl_xor_sync(0xffffffffu, v, 1);
                    v += __shfl_xor_sync(0xffffffffu, v, 2);
                    if ((l & 3) == 0)
                        atomicAdd(&racc[(mw * 32 + mt * 16 + hf * 8 + lq) * 4 + nh + sl], v);
                }
        __syncthreads();

        if (tid < TILE_M && p < N) {
            const float iz = invZ[tid];
            out[p * 3 + 0] = racc[tid * 4 + 0] * iz;
            out[p * 3 + 1] = racc[tid * 4 + 1] * iz;
            out[p * 3 + 2] = racc[tid * 4 + 2] * iz;
        }
        __syncthreads();
    }
}

extern "C" void kernel_launch(void* const* d_in, const int* in_sizes, int n_in,
                              void* d_out, int out_size)
{
    const float* X    = (const float*)d_in[0];  // [N, 6]
    const float* W    = (const float*)d_in[1];  // [768, 72]
    const float* cent = (const float*)d_in[2];  // [256, 3]
    float* out = (float*)d_out;                 // [N, 3]

    const int N = in_sizes[0] / 6;
    const int n_tiles = (N + TILE_M - 1) / TILE_M;

    int dev = 0, sms = 148;
    cudaGetDevice(&dev);
    cudaDeviceGetAttribute(&sms, cudaDevAttrMultiProcessorCount, dev);

    cudaFuncSetAttribute(rgb_hmma_kernel,
                         cudaFuncAttributeMaxDynamicSharedMemorySize, SMEM_BYTES);

    const int grid = n_tiles < sms ? n_tiles : sms;
    rgb_hmma_kernel<<<grid, TPB, SMEM_BYTES>>>(X, W, cent, out, N, n_tiles);
}

// round 8
// speedup vs baseline: 6.7271x; 1.0226x over previous
#include <cuda_runtime.h>
#include <cuda_fp16.h>
#include <stdint.h>

// rgb[n,d] = (1/Z_n) * sum_e enc[n,e] * D[n, d*72+e]
// D = A @ W',  A[n,c] = exp2(s'_nc - max_c),  s' = x[:3] . (centroid_c * log2e)
// W'[c, j=d*72+e] = W[3c+d, e]  (fp16, smem-resident)
// GEMM per 128-point tile via mma.sync.m16n8k16; 16 warps = 4m x 2k x 2n.
// enc stored transposed fp16 (pair-major) for conflict-free epilogue folds.
// Softmax: 4 lane-adjacent threads per point, scores in regs, shfl reductions.

constexpr int TPB    = 512;
constexpr int TILE_M = 128;
constexpr int NC     = 256;
constexpr int EDIM   = 72;
constexpr int NOUT   = 216;

constexpr int ROW_B  = 528;    // A/W' smem row bytes (264 halfs = 132 words, %32 = 4)
constexpr int ENC_P  = 136;    // encT row stride in half2 (8 mod 32 -> distinct banks)

constexpr int OFF_CENT = 0;                               // 4096
constexpr int OFF_WP   = 4096;                            // 216*528 = 114048
constexpr int OFF_A    = OFF_WP + NOUT * ROW_B;           // 118144
constexpr int OFF_ENC  = OFF_A + TILE_M * ROW_B;          // 185728 ; 36*136*4 = 19584
constexpr int OFF_INVZ = OFF_ENC + 36 * ENC_P * 4;        // 205312 ; 512
constexpr int OFF_RACC = OFF_INVZ + 512;                  // 205824 ; 2048
constexpr int SMEM_BYTES = OFF_RACC + 2048;               // 207872

constexpr float LOG2E = 1.4426950408889634f;

__device__ __forceinline__ uint32_t s2u(const void* p) {
    uint32_t a;
    asm("{ .reg .u64 t; cvta.to.shared.u64 t, %1; cvt.u32.u64 %0, t; }"
        : "=r"(a) : "l"(p));
    return a;
}
__device__ __forceinline__ void ldsm4(uint32_t* r, uint32_t addr) {
    asm volatile("ldmatrix.sync.aligned.m8n8.x4.shared.b16 {%0,%1,%2,%3}, [%4];"
                 : "=r"(r[0]), "=r"(r[1]), "=r"(r[2]), "=r"(r[3]) : "r"(addr));
}
__device__ __forceinline__ void ldsm2(uint32_t* r, uint32_t addr) {
    asm volatile("ldmatrix.sync.aligned.m8n8.x2.shared.b16 {%0,%1}, [%2];"
                 : "=r"(r[0]), "=r"(r[1]) : "r"(addr));
}
__device__ __forceinline__ void hmma(float& d0, float& d1, float& d2, float& d3,
                                     const uint32_t* a, const uint32_t* b) {
    asm volatile("mma.sync.aligned.m16n8k16.row.col.f32.f16.f16.f32 "
                 "{%0,%1,%2,%3}, {%4,%5,%6,%7}, {%8,%9}, {%0,%1,%2,%3};"
                 : "+f"(d0), "+f"(d1), "+f"(d2), "+f"(d3)
                 : "r"(a[0]), "r"(a[1]), "r"(a[2]), "r"(a[3]), "r"(b[0]), "r"(b[1]));
}
__device__ __forceinline__ void fold(float& acc, float d0, float d1,
                                     const __half2* et, int idx) {
    float2 e = __half22float2(et[idx]);
    acc = fmaf(d0, e.x, fmaf(d1, e.y, acc));
}

// Strip-pair: 8 ldsm4 B frags (2 strips x 8 ksteps), 32 HMMAs, fold into acc.
template<int SL0, int SL1>
__device__ __forceinline__ void gemm_pair(
    uint32_t bbase, const uint32_t (&a)[2][8][4], int eo0, int eo1,
    const __half2* et, const int* po, float (&acc)[2][2][2])
{
    float d[2][2][4];
#pragma unroll
    for (int mt = 0; mt < 2; ++mt)
#pragma unroll
        for (int st = 0; st < 2; ++st)
#pragma unroll
            for (int i = 0; i < 4; ++i) d[mt][st][i] = 0.f;

#pragma unroll
    for (int hb = 0; hb < 2; ++hb) {
        uint32_t b[4][4];
#pragma unroll
        for (int kk = 0; kk < 4; ++kk)
            ldsm4(b[kk], bbase + (hb * 4 + kk) * 32);
#pragma unroll
        for (int kk = 0; kk < 4; ++kk)
#pragma unroll
            for (int mt = 0; mt < 2; ++mt) {
                hmma(d[mt][0][0], d[mt][0][1], d[mt][0][2], d[mt][0][3],
                     a[mt][hb * 4 + kk], &b[kk][0]);
                hmma(d[mt][1][0], d[mt][1][1], d[mt][1][2], d[mt][1][3],
                     a[mt][hb * 4 + kk], &b[kk][2]);
            }
    }
    const int i0 = (eo0 >> 1) * ENC_P, i1 = (eo1 >> 1) * ENC_P;
    fold(acc[0][0][SL0], d[0][0][0], d[0][0][1], et, i0 + po[0]);
    fold(acc[0][1][SL0], d[0][0][2], d[0][0][3], et, i0 + po[1]);
    fold(acc[1][0][SL0], d[1][0][0], d[1][0][1], et, i0 + po[2]);
    fold(acc[1][1][SL0], d[1][0][2], d[1][0][3], et, i0 + po[3]);
    fold(acc[0][0][SL1], d[0][1][0], d[0][1][1], et, i1 + po[0]);
    fold(acc[0][1][SL1], d[0][1][2], d[0][1][3], et, i1 + po[1]);
    fold(acc[1][0][SL1], d[1][1][0], d[1][1][1], et, i1 + po[2]);
    fold(acc[1][1][SL1], d[1][1][2], d[1][1][3], et, i1 + po[3]);
}

template<int SL>
__device__ __forceinline__ void gemm_single(
    uint32_t bbase2, const uint32_t (&a)[2][8][4], int eo,
    const __half2* et, const int* po, float (&acc)[2][2][2])
{
    float d[2][4];
#pragma unroll
    for (int mt = 0; mt < 2; ++mt)
#pragma unroll
        for (int i = 0; i < 4; ++i) d[mt][i] = 0.f;
    uint32_t b[8][2];
#pragma unroll
    for (int kk = 0; kk < 8; ++kk) ldsm2(b[kk], bbase2 + kk * 32);
#pragma unroll
    for (int kk = 0; kk < 8; ++kk)
#pragma unroll
        for (int mt = 0; mt < 2; ++mt)
            hmma(d[mt][0], d[mt][1], d[mt][2], d[mt][3], a[mt][kk], b[kk]);
    const int i0 = (eo >> 1) * ENC_P;
    fold(acc[0][0][SL], d[0][0], d[0][1], et, i0 + po[0]);
    fold(acc[0][1][SL], d[0][2], d[0][3], et, i0 + po[1]);
    fold(acc[1][0][SL], d[1][0], d[1][1], et, i0 + po[2]);
    fold(acc[1][1][SL], d[1][2], d[1][3], et, i0 + po[3]);
}

__global__ __launch_bounds__(TPB, 1)
void rgb_hmma_kernel(const float* __restrict__ X,
                     const float* __restrict__ W,
                     const float* __restrict__ cent,
                     float* __restrict__ out, int N, int n_tiles)
{
    extern __shared__ char smem[];
    const uint32_t sb = s2u(smem);
    float4*  c4   = reinterpret_cast<float4*>(smem + OFF_CENT);
    __half*  wp   = reinterpret_cast<__half*>(smem + OFF_WP);
    __half2* atp  = reinterpret_cast<__half2*>(smem + OFF_A);
    __half2* encT = reinterpret_cast<__half2*>(smem + OFF_ENC);
    float*   invZ = reinterpret_cast<float*>(smem + OFF_INVZ);
    float*   racc = reinterpret_cast<float*>(smem + OFF_RACC);

    const int tid = threadIdx.x;

    for (int i = tid; i < NC; i += TPB) {
        float4 qv;
        qv.x = cent[i * 3 + 0] * LOG2E;
        qv.y = cent[i * 3 + 1] * LOG2E;
        qv.z = cent[i * 3 + 2] * LOG2E;
        qv.w = 0.f;
        c4[i] = qv;
    }
    for (int i = tid; i < 768 * EDIM; i += TPB) {
        int r = i / EDIM, e = i - r * EDIM;
        int c = r / 3, d = r - 3 * c;
        wp[(d * EDIM + e) * (ROW_B / 2) + c] = __float2half_rn(W[i]);
    }
    __syncthreads();

    const int pt = tid >> 2;           // point within tile
    const int q  = tid & 3;            // cluster quarter (lane-adjacent)
    const int w  = tid >> 5, l = tid & 31;
    const int mw = w & 3, kh = (w >> 2) & 1, nh = w >> 3;
    const int lq = l >> 2;

    // epilogue fold row offsets: (l&3) shifts e-pair, rows = mw*32+lq+{0,8,16,24}
    int po[4];
#pragma unroll
    for (int k = 0; k < 4; ++k) po[k] = (l & 3) * ENC_P + mw * 32 + lq + k * 8;

    for (int tile = blockIdx.x; tile < n_tiles; tile += gridDim.x) {
        const int p = tile * TILE_M + pt;

        float x0 = 0.f, x1 = 0.f, x2 = 0.f;
        if (p < N) { x0 = X[p * 6 + 0]; x1 = X[p * 6 + 1]; x2 = X[p * 6 + 2]; }

        // ---- enc: quarter q<3 computes dims 2q, 2q+1 -> transposed fp16 pairs ----
        if (q < 3) {
#pragma unroll
            for (int dd = 0; dd < 2; ++dd) {
                const int d = 2 * q + dd;
                float xv = (p < N) ? X[p * 6 + d] : 0.f;
                float sv[6], cv[6], s, c;
                __sincosf(xv, &s, &c);
#pragma unroll
                for (int k = 0; k < 6; ++k) {
                    sv[k] = s; cv[k] = c;
                    float s2 = 2.f * s * c;
                    float c2 = fmaf(-2.f * s, s, 1.f);
                    s = s2; c = c2;
                }
#pragma unroll
                for (int t = 0; t < 3; ++t) {
                    encT[(d * 6 + t) * ENC_P + pt]     = __floats2half2_rn(sv[2 * t], sv[2 * t + 1]);
                    encT[(d * 6 + 3 + t) * ENC_P + pt] = __floats2half2_rn(cv[2 * t], cv[2 * t + 1]);
                }
            }
        }

        // ---- scores into registers (64 per thread, rotated order for pack) ----
        float sreg[64];
#pragma unroll
        for (int j = 0; j < 64; ++j) {
            const int ci = (q << 6) + ((j + 2 * q) & 63);
            float4 cq = c4[ci];
            sreg[j] = fmaf(x0, cq.x, fmaf(x1, cq.y, x2 * cq.z));
        }
        float mx = sreg[0];
#pragma unroll
        for (int j = 1; j < 64; ++j) mx = fmaxf(mx, sreg[j]);
        mx = fmaxf(mx, __shfl_xor_sync(0xffffffffu, mx, 1));
        mx = fmaxf(mx, __shfl_xor_sync(0xffffffffu, mx, 2));

        // ---- exp2 + pack (conflict-free via rotation) + Z from rounded weights ----
        float z = 0.f;
#pragma unroll
        for (int j = 0; j < 64; j += 2) {
            float w0, w1;
            asm("ex2.approx.ftz.f32 %0, %1;" : "=f"(w0) : "f"(sreg[j] - mx));
            asm("ex2.approx.ftz.f32 %0, %1;" : "=f"(w1) : "f"(sreg[j + 1] - mx));
            __half2 h2 = __floats2half2_rn(w0, w1);
            z += __low2float(h2) + __high2float(h2);
            const int u = (j + 2 * q) & 63;
            atp[pt * 132 + ((q << 6) + u) / 2] = h2;
        }
        z += __shfl_xor_sync(0xffffffffu, z, 1);
        z += __shfl_xor_sync(0xffffffffu, z, 2);
        if (q == 0) invZ[pt] = __frcp_rn(z);
        racc[tid] = 0.f;
        __syncthreads();

        // ---- GEMM: warp = (m-group 32, k-half 128, n-half ~108) ----
        uint32_t a[2][8][4];
        {
            const uint32_t a_base = sb + OFF_A
                + (uint32_t)((mw * 32 + (l & 15)) * ROW_B + kh * 256 + (l >> 4) * 16);
#pragma unroll
            for (int mt = 0; mt < 2; ++mt)
#pragma unroll
                for (int kk = 0; kk < 8; ++kk)
                    ldsm4(a[mt][kk], a_base + mt * 16 * ROW_B + kk * 32);
        }

        const uint32_t bl2 = sb + OFF_WP
            + (uint32_t)((l & 7) * ROW_B + ((l >> 3) & 1) * 16 + kh * 256);
        const uint32_t bl4 = bl2 + (uint32_t)(((l >> 4) & 1) * 8 * ROW_B);

        float acc[2][2][2];
#pragma unroll
        for (int mt = 0; mt < 2; ++mt)
#pragma unroll
            for (int hf = 0; hf < 2; ++hf)
#pragma unroll
                for (int sl = 0; sl < 2; ++sl) acc[mt][hf][sl] = 0.f;

        if (nh == 0) {   // strips 0..13 : dch0 = s0..8, dch1 = s9..13
            gemm_pair<0, 0>(bl4 + 0  * 8 * ROW_B, a, 0,  8,  encT, po, acc);
            gemm_pair<0, 0>(bl4 + 2  * 8 * ROW_B, a, 16, 24, encT, po, acc);
            gemm_pair<0, 0>(bl4 + 4  * 8 * ROW_B, a, 32, 40, encT, po, acc);
            gemm_pair<0, 0>(bl4 + 6  * 8 * ROW_B, a, 48, 56, encT, po, acc);
            gemm_pair<0, 1>(bl4 + 8  * 8 * ROW_B, a, 64, 0,  encT, po, acc);
            gemm_pair<1, 1>(bl4 + 10 * 8 * ROW_B, a, 8,  16, encT, po, acc);
            gemm_pair<1, 1>(bl4 + 12 * 8 * ROW_B, a, 24, 32, encT, po, acc);
        } else {         // strips 14..26 : dch1 = s14..17, dch2 = s18..26
            gemm_pair<0, 0>(bl4 + 14 * 8 * ROW_B, a, 40, 48, encT, po, acc);
            gemm_pair<0, 0>(bl4 + 16 * 8 * ROW_B, a, 56, 64, encT, po, acc);
            gemm_pair<1, 1>(bl4 + 18 * 8 * ROW_B, a, 0,  8,  encT, po, acc);
            gemm_pair<1, 1>(bl4 + 20 * 8 * ROW_B, a, 16, 24, encT, po, acc);
            gemm_pair<1, 1>(bl4 + 22 * 8 * ROW_B, a, 32, 40, encT, po, acc);
            gemm_pair<1, 1>(bl4 + 24 * 8 * ROW_B, a, 48, 56, encT, po, acc);
            gemm_single<1>(bl2 + 26 * 8 * ROW_B, a, 64, encT, po, acc);
        }

        // ---- quad-reduce + atomic into racc[row*4 + dch] ----
#pragma unroll
        for (int mt = 0; mt < 2; ++mt)
#pragma unroll
            for (int hf = 0; hf < 2; ++hf)
#pragma unroll
                for (int sl = 0; sl < 2; ++sl) {
                    float v = acc[mt][hf][sl];
                    v += __shfl_xor_sync(0xffffffffu, v, 1);
                    v += __shfl_xor_sync(0xffffffffu, v, 2);
                    if ((l & 3) == 0)
                        atomicAdd(&racc[(mw * 32 + mt * 16 + hf * 8 + lq) * 4 + nh + sl], v);
                }
        __syncthreads();

        // ---- write out ----
        if (tid < TILE_M) {
            const int po2 = tile * TILE_M + tid;
            if (po2 < N) {
                const float iz = invZ[tid];
                out[po2 * 3 + 0] = racc[tid * 4 + 0] * iz;
                out[po2 * 3 + 1] = racc[tid * 4 + 1] * iz;
                out[po2 * 3 + 2] = racc[tid * 4 + 2] * iz;
            }
        }
        __syncthreads();
    }
}

extern "C" void kernel_launch(void* const* d_in, const int* in_sizes, int n_in,
                              void* d_out, int out_size)
{
    const float* X    = (const float*)d_in[0];  // [N, 6]
    const float* W    = (const float*)d_in[1];  // [768, 72]
    const float* cent = (const float*)d_in[2];  // [256, 3]
    float* out = (float*)d_out;                 // [N, 3]

    const int N = in_sizes[0] / 6;
    const int n_tiles = (N + TILE_M - 1) / TILE_M;

    int dev = 0, sms = 148;
    cudaGetDevice(&dev);
    cudaDeviceGetAttribute(&sms, cudaDevAttrMultiProcessorCount, dev);

    cudaFuncSetAttribute(rgb_hmma_kernel,
                         cudaFuncAttributeMaxDynamicSharedMemorySize, SMEM_BYTES);

    const int grid = n_tiles < sms ? n_tiles : sms;
    rgb_hmma_kernel<<<grid, TPB, SMEM_BYTES>>>(X, W, cent, out, N, n_tiles);
}

// round 9
// speedup vs baseline: 6.9555x; 1.0340x over previous
#include <cuda_runtime.h>
#include <cuda_fp16.h>
#include <stdint.h>

// rgb[n,d] = (1/Z_n) * sum_e enc[n,e] * D[n, d*72+e]
// D = A @ W',  A[n,c] = exp2(s'_nc - ub_n),  s' = x[:3].(centroid*log2e),
// ub_n = |x[:3]| * max_c |centroid'_c|  (upper bound; no max pass needed)
// Software-pipelined: softmax/pack(t+1) and GEMM(t) share one sync window.

constexpr int TPB    = 512;
constexpr int TILE_M = 128;
constexpr int NC     = 256;
constexpr int EDIM   = 72;
constexpr int NOUT   = 216;

constexpr int ROW_B  = 528;            // A/W' smem row bytes (132 words)
constexpr int ENC_B  = 544;            // bytes per enc e-pair row (128*4B + 32 pad)
constexpr int ENC_BUF = 36 * ENC_B;    // 19584

constexpr int OFF_CENT = 0;                          // 4096
constexpr int OFF_MRED = 4096;                       // 64 (warp-max scratch)
constexpr int OFF_WP   = 4160;                       // 216*528 = 114048
constexpr int OFF_A    = OFF_WP + NOUT * ROW_B;      // 118208
constexpr int OFF_ENC  = OFF_A + TILE_M * ROW_B;     // 185792 (x2 buffers)
constexpr int OFF_INVZ = OFF_ENC + 2 * ENC_BUF;      // 224960 (2*128 floats)
constexpr int OFF_RACC = OFF_INVZ + 1024;            // 225984 (2*512 floats)
constexpr int SMEM_BYTES = OFF_RACC + 4096;          // 230080

constexpr float LOG2E = 1.4426950408889634f;

__device__ __forceinline__ uint32_t s2u(const void* p) {
    uint32_t a;
    asm("{ .reg .u64 t; cvta.to.shared.u64 t, %1; cvt.u32.u64 %0, t; }"
        : "=r"(a) : "l"(p));
    return a;
}
__device__ __forceinline__ void ldsm4(uint32_t* r, uint32_t addr) {
    asm volatile("ldmatrix.sync.aligned.m8n8.x4.shared.b16 {%0,%1,%2,%3}, [%4];"
                 : "=r"(r[0]), "=r"(r[1]), "=r"(r[2]), "=r"(r[3]) : "r"(addr));
}
__device__ __forceinline__ void ldsm2(uint32_t* r, uint32_t addr) {
    asm volatile("ldmatrix.sync.aligned.m8n8.x2.shared.b16 {%0,%1}, [%2];"
                 : "=r"(r[0]), "=r"(r[1]) : "r"(addr));
}
__device__ __forceinline__ void lds128(uint32_t& r0, uint32_t& r1,
                                       uint32_t& r2, uint32_t& r3, uint32_t addr) {
    asm volatile("ld.shared.v4.b32 {%0,%1,%2,%3}, [%4];"
                 : "=r"(r0), "=r"(r1), "=r"(r2), "=r"(r3) : "r"(addr));
}
__device__ __forceinline__ void hmma(float& d0, float& d1, float& d2, float& d3,
                                     const uint32_t* a, const uint32_t* b) {
    asm volatile("mma.sync.aligned.m16n8k16.row.col.f32.f16.f16.f32 "
                 "{%0,%1,%2,%3}, {%4,%5,%6,%7}, {%8,%9}, {%0,%1,%2,%3};"
                 : "+f"(d0), "+f"(d1), "+f"(d2), "+f"(d3)
                 : "r"(a[0]), "r"(a[1]), "r"(a[2]), "r"(a[3]), "r"(b[0]), "r"(b[1]));
}
__device__ __forceinline__ void fold2(float& acc, float d0, float d1, uint32_t h2raw) {
    __half2 h = *reinterpret_cast<__half2*>(&h2raw);
    float2 e = __half22float2(h);
    acc = fmaf(d0, e.x, fmaf(d1, e.y, acc));
}

// Strip-pair: 8 ldsm4 B frags (2 strips x 8 ksteps), 32 HMMAs, bulk LDS.128 folds.
template<int SL0, int SL1>
__device__ __forceinline__ void gemm_pair(
    uint32_t bbase, const uint32_t (&a)[2][8][4], int eo0, int eo1,
    uint32_t eb, float (&acc)[2][2][2])
{
    float d[2][2][4];
#pragma unroll
    for (int mt = 0; mt < 2; ++mt)
#pragma unroll
        for (int st = 0; st < 2; ++st)
#pragma unroll
            for (int i = 0; i < 4; ++i) d[mt][st][i] = 0.f;

#pragma unroll
    for (int hb = 0; hb < 2; ++hb) {
        uint32_t b[4][4];
#pragma unroll
        for (int kk = 0; kk < 4; ++kk)
            ldsm4(b[kk], bbase + (hb * 4 + kk) * 32);
#pragma unroll
        for (int kk = 0; kk < 4; ++kk)
#pragma unroll
            for (int mt = 0; mt < 2; ++mt) {
                hmma(d[mt][0][0], d[mt][0][1], d[mt][0][2], d[mt][0][3],
                     a[mt][hb * 4 + kk], &b[kk][0]);
                hmma(d[mt][1][0], d[mt][1][1], d[mt][1][2], d[mt][1][3],
                     a[mt][hb * 4 + kk], &b[kk][2]);
            }
    }
    uint32_t r0, r1, r2, r3;
    lds128(r0, r1, r2, r3, eb + (uint32_t)(eo0 >> 1) * ENC_B);
    fold2(acc[0][0][SL0], d[0][0][0], d[0][0][1], r0);
    fold2(acc[0][1][SL0], d[0][0][2], d[0][0][3], r1);
    fold2(acc[1][0][SL0], d[1][0][0], d[1][0][1], r2);
    fold2(acc[1][1][SL0], d[1][0][2], d[1][0][3], r3);
    lds128(r0, r1, r2, r3, eb + (uint32_t)(eo1 >> 1) * ENC_B);
    fold2(acc[0][0][SL1], d[0][1][0], d[0][1][1], r0);
    fold2(acc[0][1][SL1], d[0][1][2], d[0][1][3], r1);
    fold2(acc[1][0][SL1], d[1][1][0], d[1][1][1], r2);
    fold2(acc[1][1][SL1], d[1][1][2], d[1][1][3], r3);
}

template<int SL>
__device__ __forceinline__ void gemm_single(
    uint32_t bbase2, const uint32_t (&a)[2][8][4], int eo,
    uint32_t eb, float (&acc)[2][2][2])
{
    float d[2][4];
#pragma unroll
    for (int mt = 0; mt < 2; ++mt)
#pragma unroll
        for (int i = 0; i < 4; ++i) d[mt][i] = 0.f;
    uint32_t b[8][2];
#pragma unroll
    for (int kk = 0; kk < 8; ++kk) ldsm2(b[kk], bbase2 + kk * 32);
#pragma unroll
    for (int kk = 0; kk < 8; ++kk)
#pragma unroll
        for (int mt = 0; mt < 2; ++mt)
            hmma(d[mt][0], d[mt][1], d[mt][2], d[mt][3], a[mt][kk], b[kk]);
    uint32_t r0, r1, r2, r3;
    lds128(r0, r1, r2, r3, eb + (uint32_t)(eo >> 1) * ENC_B);
    fold2(acc[0][0][SL], d[0][0], d[0][1], r0);
    fold2(acc[0][1][SL], d[0][2], d[0][3], r1);
    fold2(acc[1][0][SL], d[1][0], d[1][1], r2);
    fold2(acc[1][1][SL], d[1][2], d[1][3], r3);
}

__device__ __forceinline__ void load_afrags(uint32_t (&a)[2][8][4],
                                            uint32_t sb, int mw, int kh, int l)
{
    const uint32_t a_base = sb + OFF_A
        + (uint32_t)((mw * 32 + (l & 15)) * ROW_B + kh * 256 + (l >> 4) * 16);
#pragma unroll
    for (int mt = 0; mt < 2; ++mt)
#pragma unroll
        for (int kk = 0; kk < 8; ++kk)
            ldsm4(a[mt][kk], a_base + mt * 16 * ROW_B + kk * 32);
}

// Register-lean softmax + enc + A-pack for one tile (4 lane-adjacent threads/point).
__device__ __forceinline__ void softmax_pack(
    const float* __restrict__ X, const float4* __restrict__ c4,
    __half2* __restrict__ atp, __half2* __restrict__ encp,
    float* __restrict__ invZp, float Mn,
    int t, int N, int pt, int q, int gp)
{
    const int p = t * TILE_M + pt;
    float x0 = 0.f, x1 = 0.f, x2 = 0.f;
    if (p < N) { x0 = X[p * 6 + 0]; x1 = X[p * 6 + 1]; x2 = X[p * 6 + 2]; }

    if (q < 3) {
#pragma unroll
        for (int dd = 0; dd < 2; ++dd) {
            const int d = 2 * q + dd;
            float xv = (p < N) ? X[p * 6 + d] : 0.f;
            float sv[6], cv[6], s, c;
            __sincosf(xv, &s, &c);
#pragma unroll
            for (int k = 0; k < 6; ++k) {
                sv[k] = s; cv[k] = c;
                float s2 = 2.f * s * c;
                float c2 = fmaf(-2.f * s, s, 1.f);
                s = s2; c = c2;
            }
#pragma unroll
            for (int tt = 0; tt < 3; ++tt) {
                encp[(d * 6 + tt) * (ENC_B / 4) + gp]     = __floats2half2_rn(sv[2 * tt], sv[2 * tt + 1]);
                encp[(d * 6 + 3 + tt) * (ENC_B / 4) + gp] = __floats2half2_rn(cv[2 * tt], cv[2 * tt + 1]);
            }
        }
    }

    const float ub = sqrtf(fmaf(x0, x0, fmaf(x1, x1, x2 * x2))) * Mn;
    const float4* cb = c4 + (q << 6);
    float z = 0.f;
#pragma unroll 4
    for (int j = 0; j < 64; j += 2) {
        const int u0 = (j + 2 * q) & 63;
        float4 ca = cb[u0], cd = cb[u0 + 1];
        float s0 = fmaf(x0, ca.x, fmaf(x1, ca.y, x2 * ca.z)) - ub;
        float s1 = fmaf(x0, cd.x, fmaf(x1, cd.y, x2 * cd.z)) - ub;
        float w0, w1;
        asm("ex2.approx.ftz.f32 %0, %1;" : "=f"(w0) : "f"(s0));
        asm("ex2.approx.ftz.f32 %0, %1;" : "=f"(w1) : "f"(s1));
        __half2 h2 = __floats2half2_rn(w0, w1);
        z += __low2float(h2) + __high2float(h2);
        atp[pt * 132 + (((q << 6) + u0) >> 1)] = h2;
    }
    z += __shfl_xor_sync(0xffffffffu, z, 1);
    z += __shfl_xor_sync(0xffffffffu, z, 2);
    if (q == 0) invZp[pt] = __frcp_rn(z);
}

__global__ __launch_bounds__(TPB, 1)
void rgb_hmma_kernel(const float* __restrict__ X,
                     const float* __restrict__ W,
                     const float* __restrict__ cent,
                     float* __restrict__ out, int N, int n_tiles)
{
    extern __shared__ char smem[];
    const uint32_t sb = s2u(smem);
    float4*  c4   = reinterpret_cast<float4*>(smem + OFF_CENT);
    float*   mred = reinterpret_cast<float*>(smem + OFF_MRED);
    __half*  wp   = reinterpret_cast<__half*>(smem + OFF_WP);
    __half2* atp  = reinterpret_cast<__half2*>(smem + OFF_A);
    float*   invZ = reinterpret_cast<float*>(smem + OFF_INVZ);
    float*   racc = reinterpret_cast<float*>(smem + OFF_RACC);

    const int tid = threadIdx.x;
    const int w = tid >> 5, l = tid & 31;

    // ---- init: scaled centroids, W' fp16 transpose, zero racc, max-norm ----
    for (int i = tid; i < NC; i += TPB) {
        float4 qv;
        qv.x = cent[i * 3 + 0] * LOG2E;
        qv.y = cent[i * 3 + 1] * LOG2E;
        qv.z = cent[i * 3 + 2] * LOG2E;
        qv.w = 0.f;
        c4[i] = qv;
    }
    for (int i = tid; i < 768 * EDIM; i += TPB) {
        int r = i / EDIM, e = i - r * EDIM;
        int c = r / 3, d = r - 3 * c;
        wp[(d * EDIM + e) * (ROW_B / 2) + c] = __float2half_rn(W[i]);
    }
    racc[tid] = 0.f;
    racc[tid + 512] = 0.f;
    __syncthreads();

    float mn2 = 0.f;
    if (tid < NC) {
        float4 cc = c4[tid];
        mn2 = fmaf(cc.x, cc.x, fmaf(cc.y, cc.y, cc.z * cc.z));
    }
#pragma unroll
    for (int o = 16; o > 0; o >>= 1)
        mn2 = fmaxf(mn2, __shfl_xor_sync(0xffffffffu, mn2, o));
    if (l == 0) mred[w] = mn2;
    __syncthreads();
    float M2 = mred[0];
#pragma unroll
    for (int i = 1; i < 16; ++i) M2 = fmaxf(M2, mred[i]);
    const float Mn = sqrtf(M2);

    const int pt = tid >> 2;
    const int q  = tid & 3;
    const int gp = (pt >> 5) * 32 + (pt & 7) * 4 + ((pt >> 3) & 3);  // regrouped enc col
    const int mw = w & 3, kh = (w >> 2) & 1, nh = w >> 3;
    const int lq = l >> 2;
    const int G = gridDim.x;

    const uint32_t bl2 = sb + OFF_WP
        + (uint32_t)((l & 7) * ROW_B + ((l >> 3) & 1) * 16 + kh * 256);
    const uint32_t bl4 = bl2 + (uint32_t)(((l >> 4) & 1) * 8 * ROW_B);
    const uint32_t eb0 = sb + OFF_ENC
        + (uint32_t)((l & 3) * ENC_B + (mw * 32 + lq * 4) * 4);

    // ---- pipeline prologue ----
    int t = blockIdx.x;
    int par = 0;
    uint32_t a[2][8][4];
    if (t < n_tiles)
        softmax_pack(X, c4, atp,
                     reinterpret_cast<__half2*>(smem + OFF_ENC),
                     invZ, Mn, t, N, pt, q, gp);
    __syncthreads();
    if (t < n_tiles) load_afrags(a, sb, mw, kh, l);
    __syncthreads();

    for (; t < n_tiles; t += G) {
        const int tn = t + G;
        const int parn = par ^ 1;

        // window A: softmax(t+1) [math] + GEMM(t) [L1/tensor] overlap across warps
        if (tn < n_tiles)
            softmax_pack(X, c4, atp,
                         reinterpret_cast<__half2*>(smem + OFF_ENC + parn * ENC_BUF),
                         invZ + parn * TILE_M, Mn, tn, N, pt, q, gp);

        const uint32_t eb = eb0 + (uint32_t)par * ENC_BUF;
        float acc[2][2][2];
#pragma unroll
        for (int mt = 0; mt < 2; ++mt)
#pragma unroll
            for (int hf = 0; hf < 2; ++hf)
#pragma unroll
                for (int sl = 0; sl < 2; ++sl) acc[mt][hf][sl] = 0.f;

        if (nh == 0) {   // strips 0..13 : dch0 = s0..8, dch1 = s9..13
            gemm_pair<0, 0>(bl4 + 0  * 8 * ROW_B, a, 0,  8,  eb, acc);
            gemm_pair<0, 0>(bl4 + 2  * 8 * ROW_B, a, 16, 24, eb, acc);
            gemm_pair<0, 0>(bl4 + 4  * 8 * ROW_B, a, 32, 40, eb, acc);
            gemm_pair<0, 0>(bl4 + 6  * 8 * ROW_B, a, 48, 56, eb, acc);
            gemm_pair<0, 1>(bl4 + 8  * 8 * ROW_B, a, 64, 0,  eb, acc);
            gemm_pair<1, 1>(bl4 + 10 * 8 * ROW_B, a, 8,  16, eb, acc);
            gemm_pair<1, 1>(bl4 + 12 * 8 * ROW_B, a, 24, 32, eb, acc);
        } else {         // strips 14..26 : dch1 = s14..17, dch2 = s18..26
            gemm_pair<0, 0>(bl4 + 14 * 8 * ROW_B, a, 40, 48, eb, acc);
            gemm_pair<0, 0>(bl4 + 16 * 8 * ROW_B, a, 56, 64, eb, acc);
            gemm_pair<1, 1>(bl4 + 18 * 8 * ROW_B, a, 0,  8,  eb, acc);
            gemm_pair<1, 1>(bl4 + 20 * 8 * ROW_B, a, 16, 24, eb, acc);
            gemm_pair<1, 1>(bl4 + 22 * 8 * ROW_B, a, 32, 40, eb, acc);
            gemm_pair<1, 1>(bl4 + 24 * 8 * ROW_B, a, 48, 56, eb, acc);
            gemm_single<1>(bl2 + 26 * 8 * ROW_B, a, 64, eb, acc);
        }

        // quad-reduce + atomic into racc[par]
        float* raccp = racc + par * 512;
#pragma unroll
        for (int mt = 0; mt < 2; ++mt)
#pragma unroll
            for (int hf = 0; hf < 2; ++hf)
#pragma unroll
                for (int sl = 0; sl < 2; ++sl) {
                    float v = acc[mt][hf][sl];
                    v += __shfl_xor_sync(0xffffffffu, v, 1);
                    v += __shfl_xor_sync(0xffffffffu, v, 2);
                    if ((l & 3) == 0)
                        atomicAdd(&raccp[(mw * 32 + mt * 16 + hf * 8 + lq) * 4 + nh + sl], v);
                }
        __syncthreads();   // sync1: pack(t+1) & atomics(t) complete

        if (tn < n_tiles) load_afrags(a, sb, mw, kh, l);

        if (tid < TILE_M) {
            float* rp = racc + par * 512 + tid * 4;
            const int po2 = t * TILE_M + tid;
            if (po2 < N) {
                const float iz = invZ[par * TILE_M + tid];
                out[po2 * 3 + 0] = rp[0] * iz;
                out[po2 * 3 + 1] = rp[1] * iz;
                out[po2 * 3 + 2] = rp[2] * iz;
            }
            rp[0] = 0.f; rp[1] = 0.f; rp[2] = 0.f; rp[3] = 0.f;
        }
        __syncthreads();   // sync2: a-frags(t+1) loaded, racc[par] recycled

        par = parn;
    }
}

extern "C" void kernel_launch(void* const* d_in, const int* in_sizes, int n_in,
                              void* d_out, int out_size)
{
    const float* X    = (const float*)d_in[0];  // [N, 6]
    const float* W    = (const float*)d_in[1];  // [768, 72]
    const float* cent = (const float*)d_in[2];  // [256, 3]
    float* out = (float*)d_out;                 // [N, 3]

    const int N = in_sizes[0] / 6;
    const int n_tiles = (N + TILE_M - 1) / TILE_M;

    int dev = 0, sms = 148;
    cudaGetDevice(&dev);
    cudaDeviceGetAttribute(&sms, cudaDevAttrMultiProcessorCount, dev);

    cudaFuncSetAttribute(rgb_hmma_kernel,
                         cudaFuncAttributeMaxDynamicSharedMemorySize, SMEM_BYTES);

    const int grid = n_tiles < sms ? n_tiles : sms;
    rgb_hmma_kernel<<<grid, TPB, SMEM_BYTES>>>(X, W, cent, out, N, n_tiles);
}